// round 9
// baseline (speedup 1.0000x reference)
#include <cuda_runtime.h>
#include <cstdint>

// out[100000,128] = x[100000,128] @ (Wc+Wn)[128,128] + b[128]
// (gamma/segment-sum in the reference is dead code; edge_index unused)
//
// tf32 mma.sync (m16n8k8). CTA 128x128, 8 warps of 32x64, 2 CTAs/SM.
// W pre-swizzled into MMA-fragment order (unit-stride LDS.64).
// x streamed in K=32 cp.async chunks, 3-stage pipeline (2 chunks in flight),
// XOR-swizzled x smem (no padding) -> 112KB smem total.
//
// Inputs: d_in[0]=x f32 [100000,128], d_in[1]=edge_index i64 (UNUSED),
//         d_in[2]=Wc f32 [128,128], d_in[3]=Wn f32 [128,128], d_in[4]=b f32 [128]

#define D 128
#define TILE_M 128
#define KC 32
#define XBUF (TILE_M * KC)       // 4096 floats = 16KB per x stage
#define WCH 4096                 // W floats per chunk, frag-ordered

// W fragment image: idx = ((((c*2+wn)*4+s)*8+j)*32+lane)*2+h
//   n = wn*64 + j*8 + (lane>>2), k = c*32 + s*8 + (lane&3) + 4*h
__device__ float g_Wt[D * D];

__device__ __forceinline__ float to_tf32(float f) {
    float r;
    asm("cvt.rna.tf32.f32 %0, %1;" : "=f"(r) : "f"(f));
    return r;
}

__global__ void prep_w_kernel(const float* __restrict__ Wc,
                              const float* __restrict__ Wn) {
    int i = blockIdx.x * blockDim.x + threadIdx.x;
    if (i >= D * D) return;
    int h = i & 1, lane = (i >> 1) & 31, j = (i >> 6) & 7;
    int s = (i >> 9) & 3, wn = (i >> 11) & 1, c = i >> 12;
    int n = wn * 64 + j * 8 + (lane >> 2);
    int k = c * 32 + s * 8 + (lane & 3) + 4 * h;
    g_Wt[i] = to_tf32(Wc[k * D + n] + Wn[k * D + n]);
}

#define MMA_TF32(c, a0, a1, a2, a3, b0, b1)                                   \
    asm volatile(                                                             \
        "mma.sync.aligned.m16n8k8.row.col.f32.tf32.tf32.f32 "                 \
        "{%0,%1,%2,%3}, {%4,%5,%6,%7}, {%8,%9}, {%0,%1,%2,%3};"               \
        : "+f"((c)[0]), "+f"((c)[1]), "+f"((c)[2]), "+f"((c)[3])              \
        : "r"(a0), "r"(a1), "r"(a2), "r"(a3), "r"(b0), "r"(b1))

__device__ __forceinline__ void cp_async16(uint32_t dst, const void* src, int valid) {
    asm volatile("cp.async.cg.shared.global [%0], [%1], 16, %2;"
                 :: "r"(dst), "l"(src), "r"(valid ? 16 : 0));
}

__global__ __launch_bounds__(256, 2)
void gemm_tf32_kernel(const float* __restrict__ x,
                      const float* __restrict__ bias,
                      float* __restrict__ out, int nrows) {
    extern __shared__ float sm[];
    float* xs = sm;                  // [3][4096]  x pipeline, XOR-swizzled
    float* ws = sm + 3 * XBUF;       // [4][4096]  frag-ordered W

    const int tid = threadIdx.x;
    const int lane = tid & 31;
    const int wid = tid >> 5;
    const int g = lane >> 2;
    const int t4 = lane & 3;
    const int wm = wid >> 1;         // 0..3
    const int wn = wid & 1;          // 0..1
    const int row0 = blockIdx.x * TILE_M;

    const int lr = tid >> 3;         // 0..31
    const int lq = tid & 7;          // float4 column 0..7
    const int lk = lq << 2;

    const uint32_t xs_b = (uint32_t)__cvta_generic_to_shared(xs);
    const uint32_t ws_b = (uint32_t)__cvta_generic_to_shared(ws);

    // x chunk load with XOR swizzle: dst float4 idx = r*8 + (q ^ (r&7))
    auto load_x_chunk = [&](int k0, int buf) {
        uint32_t xd = xs_b + (uint32_t)(buf * XBUF) * 4;
#pragma unroll
        for (int it = 0; it < 4; it++) {
            int r = lr + 32 * it;
            int grow = row0 + r;
            uint32_t f4 = (uint32_t)(r * 8 + (lq ^ (r & 7)));
            cp_async16(xd + f4 * 16, x + (size_t)grow * D + k0 + lk, grow < nrows);
        }
        asm volatile("cp.async.commit_group;" ::: "memory");
    };

    // ---- prologue: group W | x0 | x1 ----
#pragma unroll
    for (int it = 0; it < 16; it++) {  // 4096 float4s of W
        int idx = tid + 256 * it;
        cp_async16(ws_b + (uint32_t)idx * 16, g_Wt + ((size_t)idx << 2), 1);
    }
    asm volatile("cp.async.commit_group;" ::: "memory");
    load_x_chunk(0, 0);
    load_x_chunk(KC, 1);

    float acc[2][8][4];
#pragma unroll
    for (int i = 0; i < 2; i++)
#pragma unroll
        for (int j = 0; j < 8; j++)
#pragma unroll
            for (int p = 0; p < 4; p++) acc[i][j][p] = 0.0f;

    const float* wb_base = ws + wn * 2048 + lane * 2;
    const int rowb = (wm * 32 + g) * 32 + t4;   // float offset base (i=0,p=0,h-term sep)

#pragma unroll
    for (int c = 0; c < 4; c++) {
        // chunk c is the oldest x group; allow chunk c+1 to remain in flight
        if (c < 3)
            asm volatile("cp.async.wait_group 1;" ::: "memory");
        else
            asm volatile("cp.async.wait_group 0;" ::: "memory");
        __syncthreads();
        if (c + 2 < 4) load_x_chunk((c + 2) * KC, (c + 2) % 3);  // after sync: safe

        const float* xb = xs + (c % 3) * XBUF;
        const float* wb = wb_base + c * WCH;

#pragma unroll
        for (int s = 0; s < 4; s++) {
            const int e0 = ((2 * s) ^ g) << 2;        // xor column for h=0
            const int e1 = ((2 * s + 1) ^ g) << 2;    // xor column for h=1
            uint32_t a[2][4];
#pragma unroll
            for (int i = 0; i < 2; i++) {
                const float* xr = xb + rowb + i * 512;
                a[i][0] = __float_as_uint(xr[e0]);
                a[i][1] = __float_as_uint(xr[256 + e0]);
                a[i][2] = __float_as_uint(xr[e1]);
                a[i][3] = __float_as_uint(xr[256 + e1]);
            }
            uint32_t b[8][2];
#pragma unroll
            for (int j = 0; j < 8; j++) {
                float2 v = *(const float2*)(wb + s * 512 + j * 64);
                b[j][0] = __float_as_uint(v.x);
                b[j][1] = __float_as_uint(v.y);
            }
#pragma unroll
            for (int i = 0; i < 2; i++)
#pragma unroll
                for (int j = 0; j < 8; j++)
                    MMA_TF32(acc[i][j], a[i][0], a[i][1], a[i][2], a[i][3],
                             b[j][0], b[j][1]);
        }
    }

    // ---- epilogue: bias + store directly from accumulators ----
#pragma unroll
    for (int j = 0; j < 8; j++) {
        int col = wn * 64 + 8 * j + 2 * t4;
        float b0 = __ldg(bias + col), b1 = __ldg(bias + col + 1);
#pragma unroll
        for (int i = 0; i < 2; i++) {
            int r_lo = row0 + wm * 32 + 16 * i + g;
            int r_hi = r_lo + 8;
            if (r_lo < nrows) {
                float2 v = make_float2(acc[i][j][0] + b0, acc[i][j][1] + b1);
                *(float2*)(out + (size_t)r_lo * D + col) = v;
            }
            if (r_hi < nrows) {
                float2 v = make_float2(acc[i][j][2] + b0, acc[i][j][3] + b1);
                *(float2*)(out + (size_t)r_hi * D + col) = v;
            }
        }
    }
}

extern "C" void kernel_launch(void* const* d_in, const int* in_sizes, int n_in,
                              void* d_out, int out_size) {
    const float* x    = (const float*)d_in[0];
    const float* Wc   = (const float*)d_in[2];
    const float* Wn   = (const float*)d_in[3];
    const float* bias = (const float*)d_in[4];
    float* out = (float*)d_out;

    const int nrows = in_sizes[0] / D;                 // 100000

    prep_w_kernel<<<(D * D + 255) / 256, 256>>>(Wc, Wn);

    const int smem_bytes = (3 * XBUF + 4 * WCH) * 4;   // 114,688 - wait: 7*4096*4 = 114,688? no: 3+4=7 chunks *16KB = 112KB
    cudaFuncSetAttribute(gemm_tf32_kernel,
                         cudaFuncAttributeMaxDynamicSharedMemorySize, smem_bytes);

    int grid = (nrows + TILE_M - 1) / TILE_M;          // 782
    gemm_tf32_kernel<<<grid, 256, smem_bytes>>>(x, bias, out, nrows);
}